// round 1
// baseline (speedup 1.0000x reference)
#include <cuda_runtime.h>
#include <math.h>

#define BB 16
#define LL 1024
#define HH 1024
#define NN 64

// scratch (device globals — no allocation allowed)
__device__ float g_kernT[LL * HH];          // kern transposed: [l][h]
__device__ float g_y[BB * LL * HH];         // post-gelu activations

// ---------------------------------------------------------------------------
// Kernel 1: S4D kernel generation.
// kern[h,l] = 2 * Re( sum_n coef[h,n] * w[h,n]^l ),  w = exp(dt*A)
// One warp per h. Each lane owns n = lane and n = lane+32. Geometric
// recurrence over l, warp butterfly reduce of the real parts each step.
// ---------------------------------------------------------------------------
__global__ void k_gen(const float* __restrict__ log_dt,
                      const float* __restrict__ Arl,
                      const float* __restrict__ Aim,
                      const float* __restrict__ Cr,
                      const float* __restrict__ Ci,
                      float* __restrict__ kernT) {
    int h = blockIdx.x;
    int lane = threadIdx.x;
    float dt = expf(log_dt[h]);

    float zr[2], zi[2], wr[2], wi[2];
#pragma unroll
    for (int t = 0; t < 2; t++) {
        int n = lane + t * 32;
        float ar = -expf(Arl[h * NN + n]);
        float ai = Aim[h * NN + n];
        float dr = dt * ar, di = dt * ai;
        float er = expf(dr);
        float sn, cs;
        sincosf(di, &sn, &cs);
        float Er = er * cs - 1.0f;     // exp(dtA) - 1
        float Ei = er * sn;
        float inv = 1.0f / (ar * ar + ai * ai);
        float Fr = (Er * ar + Ei * ai) * inv;   // (exp(dtA)-1)/A
        float Fi = (Ei * ar - Er * ai) * inv;
        float cr = Cr[h * NN + n], ci = Ci[h * NN + n];
        zr[t] = cr * Fr - ci * Fi;     // coef = C * F   (z at l=0)
        zi[t] = cr * Fi + ci * Fr;
        wr[t] = er * cs;               // w = exp(dtA)
        wi[t] = er * sn;
    }

    for (int l = 0; l < LL; l++) {
        float s = zr[0] + zr[1];
#pragma unroll
        for (int o = 16; o > 0; o >>= 1)
            s += __shfl_xor_sync(0xffffffffu, s, o);
        if (lane == 0) kernT[(size_t)l * HH + h] = 2.0f * s;
#pragma unroll
        for (int t = 0; t < 2; t++) {
            float tr = zr[t] * wr[t] - zi[t] * wi[t];
            zi[t] = zr[t] * wi[t] + zi[t] * wr[t];
            zr[t] = tr;
        }
    }
}

// ---------------------------------------------------------------------------
// Kernel 2: causal conv + D-skip + gelu(tanh approx, matching jax default).
// y[b,l,h] = gelu( sum_{j=0..l} kern[h,j]*x[b,l-j,h] + x[b,l,h]*D[h] )
// Tile: 128 l x 32 h per block, j chunks of 64. Per thread: 8 l x 4 h,
// register sliding window over x (8 float4) -> 32 FFMA per 2 LDS.128.
// ---------------------------------------------------------------------------
#define CLT 128
#define CHT 32
#define CJC 64

__device__ __forceinline__ float gelu_tanh(float t) {
    float c = 0.7978845608028654f * (t + 0.044715f * t * t * t);
    return 0.5f * t * (1.0f + tanhf(c));
}

__global__ __launch_bounds__(128) void k_conv(const float* __restrict__ x,
                                              const float* __restrict__ kernT,
                                              const float* __restrict__ D,
                                              float* __restrict__ y) {
    __shared__ float ks[CJC][CHT];        // [j][h]
    __shared__ float xs[192][CHT];        // [row][h]

    int tid = threadIdx.x;
    int hg = tid & 7;       // 8 h-groups of 4
    int lg = tid >> 3;      // 16 l-groups of 8
    int hb = hg * 4;
    int lb = lg * 8;

    int H0 = blockIdx.x * CHT;
    int L0 = blockIdx.y * CLT;
    int b  = blockIdx.z;
    const float* xb = x + (size_t)b * LL * HH;

    float acc[8][4];
#pragma unroll
    for (int r = 0; r < 8; r++)
#pragma unroll
        for (int c = 0; c < 4; c++) acc[r][c] = 0.0f;

    for (int J0 = 0; J0 < L0 + CLT; J0 += CJC) {
        __syncthreads();
        // load kern chunk [64 j][32 h]
#pragma unroll
        for (int f = tid; f < 512; f += 128) {
            int j = f >> 3, h4 = (f & 7) * 4;
            *(float4*)&ks[j][h4] =
                *(const float4*)&kernT[(size_t)(J0 + j) * HH + H0 + h4];
        }
        // load x rows [xbase .. xbase+191], zero-padded OOB (handles causality)
        int xbase = L0 - J0 - 63;
#pragma unroll
        for (int f = tid; f < 192 * 8; f += 128) {
            int row = f >> 3, h4 = (f & 7) * 4;
            int gl = xbase + row;
            float4 v = make_float4(0.f, 0.f, 0.f, 0.f);
            if (gl >= 0 && gl < LL)
                v = *(const float4*)&xb[(size_t)gl * HH + H0 + h4];
            *(float4*)&xs[row][h4] = v;
        }
        __syncthreads();

        // init sliding window: row (lb + 63 - jj + r) lives in slot ((63-jj+r)&7)
        float4 win[8];
#pragma unroll
        for (int i = 0; i < 8; i++)
            win[(63 + i) & 7] = *(float4*)&xs[lb + 63 + i][hb];

#pragma unroll 1
        for (int jj0 = 0; jj0 < 64; jj0 += 8) {
#pragma unroll
            for (int u = 0; u < 8; u++) {
                int jj = jj0 + u;
                float4 kf = *(float4*)&ks[jj][hb];
#pragma unroll
                for (int r = 0; r < 8; r++) {
                    float4 xv = win[(63 - u + r) & 7];
                    acc[r][0] += kf.x * xv.x;
                    acc[r][1] += kf.y * xv.y;
                    acc[r][2] += kf.z * xv.z;
                    acc[r][3] += kf.w * xv.w;
                }
                if (jj < 63)
                    win[(62 - u) & 7] = *(float4*)&xs[lb + 62 - jj][hb];
            }
        }
    }

    // epilogue: + x*D, gelu, store
    float4 dv = *(const float4*)&D[H0 + hb];
    float dd[4] = {dv.x, dv.y, dv.z, dv.w};
#pragma unroll
    for (int r = 0; r < 8; r++) {
        int l = L0 + lb + r;
        float4 xv = *(const float4*)&xb[(size_t)l * HH + H0 + hb];
        float xa[4] = {xv.x, xv.y, xv.z, xv.w};
#pragma unroll
        for (int c = 0; c < 4; c++) {
            float t = acc[r][c] + xa[c] * dd[c];
            y[(size_t)b * LL * HH + (size_t)l * HH + H0 + hb + c] = gelu_tanh(t);
        }
    }
}

// ---------------------------------------------------------------------------
// Kernel 3: z = Y @ W + b, then GLU: out[:, :H] = z_a * sigmoid(z_g).
// M=16384, K=1024. Block computes 128 m x (64 a-cols + 64 g-cols paired).
// Double-buffered smem, 8x8 per-thread microtile.
// ---------------------------------------------------------------------------
__global__ __launch_bounds__(256) void k_gemm(const float* __restrict__ Y,
                                              const float* __restrict__ W,
                                              const float* __restrict__ bias,
                                              float* __restrict__ out) {
    __shared__ float Ys[2][16][132];   // [buf][k][m], padded
    __shared__ float Ws[2][16][128];   // [buf][k][n]  n<64: a-half, n>=64: g-half

    int tid = threadIdx.x;
    int tx = tid & 15;
    int ty = tid >> 4;
    int N0 = blockIdx.x * 64;
    int M0 = blockIdx.y * 128;

    float acc[8][8];
#pragma unroll
    for (int i = 0; i < 8; i++)
#pragma unroll
        for (int j = 0; j < 8; j++) acc[i][j] = 0.0f;

    float4 yv[2], wv[2];

#define GEMM_ISSUE_LOADS(KC)                                                   \
    {                                                                          \
        int K0 = (KC) * 16;                                                    \
        _Pragma("unroll") for (int i = 0; i < 2; i++) {                        \
            int f = tid + i * 256;                                             \
            int m = f >> 2, kq = f & 3;                                        \
            yv[i] = *(const float4*)&Y[(size_t)(M0 + m) * 1024 + K0 + kq * 4]; \
        }                                                                      \
        _Pragma("unroll") for (int i = 0; i < 2; i++) {                        \
            int f = tid + i * 256;                                             \
            int k = f >> 5, nq = f & 31;                                       \
            int n4 = nq * 4;                                                   \
            int col = (n4 < 64) ? (N0 + n4) : (1024 + N0 + n4 - 64);           \
            wv[i] = *(const float4*)&W[(size_t)(K0 + k) * 2048 + col];         \
        }                                                                      \
    }

#define GEMM_STORE_SMEM(BUF)                                                   \
    {                                                                          \
        _Pragma("unroll") for (int i = 0; i < 2; i++) {                        \
            int f = tid + i * 256;                                             \
            int m = f >> 2, kq = f & 3;                                        \
            Ys[BUF][kq * 4 + 0][m] = yv[i].x;                                  \
            Ys[BUF][kq * 4 + 1][m] = yv[i].y;                                  \
            Ys[BUF][kq * 4 + 2][m] = yv[i].z;                                  \
            Ys[BUF][kq * 4 + 3][m] = yv[i].w;                                  \
            int k = f >> 5, nq = f & 31;                                       \
            *(float4*)&Ws[BUF][k][nq * 4] = wv[i];                             \
        }                                                                      \
    }

    GEMM_ISSUE_LOADS(0);
    GEMM_STORE_SMEM(0);
    __syncthreads();

    int buf = 0;
    for (int kc = 0; kc < 64; kc++) {
        if (kc < 63) GEMM_ISSUE_LOADS(kc + 1);
#pragma unroll
        for (int k = 0; k < 16; k++) {
            float4 a0 = *(float4*)&Ys[buf][k][ty * 4];
            float4 a1 = *(float4*)&Ys[buf][k][64 + ty * 4];
            float4 b0 = *(float4*)&Ws[buf][k][tx * 4];
            float4 b1 = *(float4*)&Ws[buf][k][64 + tx * 4];
            float am[8] = {a0.x, a0.y, a0.z, a0.w, a1.x, a1.y, a1.z, a1.w};
            float bn[8] = {b0.x, b0.y, b0.z, b0.w, b1.x, b1.y, b1.z, b1.w};
#pragma unroll
            for (int i = 0; i < 8; i++)
#pragma unroll
                for (int j = 0; j < 8; j++) acc[i][j] += am[i] * bn[j];
        }
        if (kc < 63) GEMM_STORE_SMEM(buf ^ 1);
        __syncthreads();
        buf ^= 1;
    }

    // epilogue: bias + GLU
#pragma unroll
    for (int i = 0; i < 8; i++) {
        int m = M0 + ((i < 4) ? (ty * 4 + i) : (64 + ty * 4 + i - 4));
#pragma unroll
        for (int j = 0; j < 4; j++) {
            int col = N0 + tx * 4 + j;
            float za = acc[i][j] + bias[col];
            float zg = acc[i][j + 4] + bias[1024 + col];
            float sg = 1.0f / (1.0f + expf(-zg));
            out[(size_t)m * 1024 + col] = za * sg;
        }
    }
}

// ---------------------------------------------------------------------------
extern "C" void kernel_launch(void* const* d_in, const int* in_sizes, int n_in,
                              void* d_out, int out_size) {
    const float* x      = (const float*)d_in[0];  // [16,1024,1024]
    const float* log_dt = (const float*)d_in[1];  // [1024]
    const float* Arl    = (const float*)d_in[2];  // [1024,64]
    const float* Aim    = (const float*)d_in[3];  // [1024,64]
    const float* Cr     = (const float*)d_in[4];  // [1024,64]
    const float* Ci     = (const float*)d_in[5];  // [1024,64]
    const float* D      = (const float*)d_in[6];  // [1024]
    const float* W      = (const float*)d_in[7];  // [1024,2048]
    const float* bias   = (const float*)d_in[8];  // [2048]
    float* out = (float*)d_out;                   // [16,1024,1024]

    float* kernT;
    float* yy;
    cudaGetSymbolAddress((void**)&kernT, g_kernT);
    cudaGetSymbolAddress((void**)&yy, g_y);

    // 1. kernel generation
    k_gen<<<HH, 32>>>(log_dt, Arl, Aim, Cr, Ci, kernT);

    // 2. causal conv + skip + gelu
    dim3 cgrid(HH / CHT, LL / CLT, BB);
    k_conv<<<cgrid, 128>>>(x, kernT, D, yy);

    // 3. output projection + GLU
    dim3 ggrid(1024 / 64, (BB * LL) / 128);
    k_gemm<<<ggrid, 256>>>(yy, W, bias, out);
}

// round 2
// speedup vs baseline: 1.0120x; 1.0120x over previous
#include <cuda_runtime.h>
#include <math.h>

#define BB 16
#define LL 1024
#define HH 1024
#define NN 64

// scratch (device globals — no allocation allowed)
__device__ float g_kernT[LL * HH];          // kern transposed: [l][h]
__device__ float g_y[BB * LL * HH];         // post-gelu activations

// ---- packed fp32x2 helpers (SASS FFMA2 — only reachable via PTX) ----------
__device__ __forceinline__ unsigned long long pack2(float a, float b) {
    unsigned long long r;
    asm("mov.b64 %0, {%1,%2};" : "=l"(r) : "f"(a), "f"(b));
    return r;
}
__device__ __forceinline__ unsigned long long ffma2(unsigned long long a,
                                                    unsigned long long b,
                                                    unsigned long long c) {
    unsigned long long d;
    asm("fma.rn.f32x2 %0, %1, %2, %3;" : "=l"(d) : "l"(a), "l"(b), "l"(c));
    return d;
}
__device__ __forceinline__ float2 unpack2(unsigned long long v) {
    float x, y;
    asm("mov.b64 {%0,%1}, %2;" : "=f"(x), "=f"(y) : "l"(v));
    return make_float2(x, y);
}

// ---------------------------------------------------------------------------
// Kernel 1: S4D kernel generation.
// kern[h,l] = 2 * Re( sum_n coef[h,n] * w[h,n]^l ),  w = exp(dt*A)
// One warp per h; geometric recurrence + warp reduce.
// ---------------------------------------------------------------------------
__global__ void k_gen(const float* __restrict__ log_dt,
                      const float* __restrict__ Arl,
                      const float* __restrict__ Aim,
                      const float* __restrict__ Cr,
                      const float* __restrict__ Ci,
                      float* __restrict__ kernT) {
    int h = blockIdx.x;
    int lane = threadIdx.x;
    float dt = expf(log_dt[h]);

    float zr[2], zi[2], wr[2], wi[2];
#pragma unroll
    for (int t = 0; t < 2; t++) {
        int n = lane + t * 32;
        float ar = -expf(Arl[h * NN + n]);
        float ai = Aim[h * NN + n];
        float dr = dt * ar, di = dt * ai;
        float er = expf(dr);
        float sn, cs;
        sincosf(di, &sn, &cs);
        float Er = er * cs - 1.0f;
        float Ei = er * sn;
        float inv = 1.0f / (ar * ar + ai * ai);
        float Fr = (Er * ar + Ei * ai) * inv;
        float Fi = (Ei * ar - Er * ai) * inv;
        float cr = Cr[h * NN + n], ci = Ci[h * NN + n];
        zr[t] = cr * Fr - ci * Fi;
        zi[t] = cr * Fi + ci * Fr;
        wr[t] = er * cs;
        wi[t] = er * sn;
    }

    for (int l = 0; l < LL; l++) {
        float s = zr[0] + zr[1];
#pragma unroll
        for (int o = 16; o > 0; o >>= 1)
            s += __shfl_xor_sync(0xffffffffu, s, o);
        if (lane == 0) kernT[(size_t)l * HH + h] = 2.0f * s;
#pragma unroll
        for (int t = 0; t < 2; t++) {
            float tr = zr[t] * wr[t] - zi[t] * wi[t];
            zi[t] = zr[t] * wi[t] + zi[t] * wr[t];
            zr[t] = tr;
        }
    }
}

// ---------------------------------------------------------------------------
// Kernel 2: causal conv + D-skip + gelu, FFMA2 inner loop.
// ---------------------------------------------------------------------------
#define CLT 128
#define CHT 32
#define CJC 64

__device__ __forceinline__ float gelu_tanh(float t) {
    float c = 0.7978845608028654f * (t + 0.044715f * t * t * t);
    return 0.5f * t * (1.0f + tanhf(c));
}

__global__ __launch_bounds__(128) void k_conv(const float* __restrict__ x,
                                              const float* __restrict__ kernT,
                                              const float* __restrict__ D,
                                              float* __restrict__ y) {
    __shared__ float ks[CJC][CHT];        // [j][h]
    __shared__ float xs[192][CHT];        // [row][h]

    int tid = threadIdx.x;
    int hg = tid & 7;
    int lg = tid >> 3;
    int hb = hg * 4;
    int lb = lg * 8;

    int H0 = blockIdx.x * CHT;
    int L0 = blockIdx.y * CLT;
    int b  = blockIdx.z;
    const float* xb = x + (size_t)b * LL * HH;

    unsigned long long acc2[8][2];
#pragma unroll
    for (int r = 0; r < 8; r++) {
        acc2[r][0] = 0ull;
        acc2[r][1] = 0ull;
    }

    for (int J0 = 0; J0 < L0 + CLT; J0 += CJC) {
        __syncthreads();
#pragma unroll
        for (int f = tid; f < 512; f += 128) {
            int j = f >> 3, h4 = (f & 7) * 4;
            *(float4*)&ks[j][h4] =
                *(const float4*)&kernT[(size_t)(J0 + j) * HH + H0 + h4];
        }
        int xbase = L0 - J0 - 63;
#pragma unroll
        for (int f = tid; f < 192 * 8; f += 128) {
            int row = f >> 3, h4 = (f & 7) * 4;
            int gl = xbase + row;
            float4 v = make_float4(0.f, 0.f, 0.f, 0.f);
            if (gl >= 0 && gl < LL)
                v = *(const float4*)&xb[(size_t)gl * HH + H0 + h4];
            *(float4*)&xs[row][h4] = v;
        }
        __syncthreads();

        // sliding window as packed f32x2 pairs
        ulonglong2 win[8];
#pragma unroll
        for (int i = 0; i < 8; i++)
            win[(63 + i) & 7] = *(ulonglong2*)&xs[lb + 63 + i][hb];

#pragma unroll 1
        for (int jj0 = 0; jj0 < 64; jj0 += 8) {
#pragma unroll
            for (int u = 0; u < 8; u++) {
                int jj = jj0 + u;
                ulonglong2 kp = *(ulonglong2*)&ks[jj][hb];
#pragma unroll
                for (int r = 0; r < 8; r++) {
                    ulonglong2 xv = win[(63 - u + r) & 7];
                    acc2[r][0] = ffma2(kp.x, xv.x, acc2[r][0]);
                    acc2[r][1] = ffma2(kp.y, xv.y, acc2[r][1]);
                }
                if (jj < 63)
                    win[(62 - u) & 7] = *(ulonglong2*)&xs[lb + 62 - jj][hb];
            }
        }
    }

    // epilogue: + x*D, gelu, store
    float4 dv = *(const float4*)&D[H0 + hb];
    float dd[4] = {dv.x, dv.y, dv.z, dv.w};
#pragma unroll
    for (int r = 0; r < 8; r++) {
        int l = L0 + lb + r;
        float4 xv = *(const float4*)&xb[(size_t)l * HH + H0 + hb];
        float xa[4] = {xv.x, xv.y, xv.z, xv.w};
        float2 p0 = unpack2(acc2[r][0]);
        float2 p1 = unpack2(acc2[r][1]);
        float av[4] = {p0.x, p0.y, p1.x, p1.y};
#pragma unroll
        for (int c = 0; c < 4; c++) {
            float t = av[c] + xa[c] * dd[c];
            y[(size_t)b * LL * HH + (size_t)l * HH + H0 + hb + c] = gelu_tanh(t);
        }
    }
}

// ---------------------------------------------------------------------------
// Kernel 3: z = Y @ W + b, then GLU. FFMA2 microkernel.
// Block: 128 m x (64 a-cols paired with 64 g-cols). Thread: 8m x 8n (4 pairs x2).
// ---------------------------------------------------------------------------
__global__ __launch_bounds__(256) void k_gemm(const float* __restrict__ Y,
                                              const float* __restrict__ W,
                                              const float* __restrict__ bias,
                                              float* __restrict__ out) {
    __shared__ float Ys[2][16][132];   // [buf][k][m], padded
    __shared__ float Ws[2][16][128];   // [buf][k][n]  n<64: a-half, n>=64: g-half

    int tid = threadIdx.x;
    int tx = tid & 15;
    int ty = tid >> 4;
    int N0 = blockIdx.x * 64;
    int M0 = blockIdx.y * 128;

    unsigned long long acc2[8][4];
#pragma unroll
    for (int i = 0; i < 8; i++)
#pragma unroll
        for (int j = 0; j < 4; j++) acc2[i][j] = 0ull;

    float4 yv[2], wv[2];

#define GEMM_ISSUE_LOADS(KC)                                                   \
    {                                                                          \
        int K0 = (KC) * 16;                                                    \
        _Pragma("unroll") for (int i = 0; i < 2; i++) {                        \
            int f = tid + i * 256;                                             \
            int m = f >> 2, kq = f & 3;                                        \
            yv[i] = *(const float4*)&Y[(size_t)(M0 + m) * 1024 + K0 + kq * 4]; \
        }                                                                      \
        _Pragma("unroll") for (int i = 0; i < 2; i++) {                        \
            int f = tid + i * 256;                                             \
            int k = f >> 5, nq = f & 31;                                       \
            int n4 = nq * 4;                                                   \
            int col = (n4 < 64) ? (N0 + n4) : (1024 + N0 + n4 - 64);           \
            wv[i] = *(const float4*)&W[(size_t)(K0 + k) * 2048 + col];         \
        }                                                                      \
    }

#define GEMM_STORE_SMEM(BUF)                                                   \
    {                                                                          \
        _Pragma("unroll") for (int i = 0; i < 2; i++) {                        \
            int f = tid + i * 256;                                             \
            int m = f >> 2, kq = f & 3;                                        \
            Ys[BUF][kq * 4 + 0][m] = yv[i].x;                                  \
            Ys[BUF][kq * 4 + 1][m] = yv[i].y;                                  \
            Ys[BUF][kq * 4 + 2][m] = yv[i].z;                                  \
            Ys[BUF][kq * 4 + 3][m] = yv[i].w;                                  \
            int k = f >> 5, nq = f & 31;                                       \
            *(float4*)&Ws[BUF][k][nq * 4] = wv[i];                             \
        }                                                                      \
    }

    GEMM_ISSUE_LOADS(0);
    GEMM_STORE_SMEM(0);
    __syncthreads();

    int buf = 0;
    for (int kc = 0; kc < 64; kc++) {
        if (kc < 63) GEMM_ISSUE_LOADS(kc + 1);
#pragma unroll
        for (int k = 0; k < 16; k++) {
            float4 a0 = *(float4*)&Ys[buf][k][ty * 4];
            float4 a1 = *(float4*)&Ys[buf][k][64 + ty * 4];
            ulonglong2 bp0 = *(ulonglong2*)&Ws[buf][k][tx * 4];        // a-half
            ulonglong2 bp1 = *(ulonglong2*)&Ws[buf][k][64 + tx * 4];   // g-half
            float am[8] = {a0.x, a0.y, a0.z, a0.w, a1.x, a1.y, a1.z, a1.w};
            unsigned long long bn[4] = {bp0.x, bp0.y, bp1.x, bp1.y};
#pragma unroll
            for (int i = 0; i < 8; i++) {
                unsigned long long a2 = pack2(am[i], am[i]);
#pragma unroll
                for (int j = 0; j < 4; j++)
                    acc2[i][j] = ffma2(a2, bn[j], acc2[i][j]);
            }
        }
        if (kc < 63) GEMM_STORE_SMEM(buf ^ 1);
        __syncthreads();
        buf ^= 1;
    }

    // epilogue: bias + GLU.  acc2[i][0..1] = a-half pairs, acc2[i][2..3] = g-half
#pragma unroll
    for (int i = 0; i < 8; i++) {
        int m = M0 + ((i < 4) ? (ty * 4 + i) : (64 + ty * 4 + i - 4));
#pragma unroll
        for (int p = 0; p < 2; p++) {
            float2 za2 = unpack2(acc2[i][p]);
            float2 zg2 = unpack2(acc2[i][p + 2]);
            float za[2] = {za2.x, za2.y};
            float zg[2] = {zg2.x, zg2.y};
#pragma unroll
            for (int e = 0; e < 2; e++) {
                int col = N0 + tx * 4 + p * 2 + e;
                float a = za[e] + bias[col];
                float g = zg[e] + bias[1024 + col];
                float sg = 1.0f / (1.0f + expf(-g));
                out[(size_t)m * 1024 + col] = a * sg;
            }
        }
    }
}

// ---------------------------------------------------------------------------
extern "C" void kernel_launch(void* const* d_in, const int* in_sizes, int n_in,
                              void* d_out, int out_size) {
    const float* x      = (const float*)d_in[0];
    const float* log_dt = (const float*)d_in[1];
    const float* Arl    = (const float*)d_in[2];
    const float* Aim    = (const float*)d_in[3];
    const float* Cr     = (const float*)d_in[4];
    const float* Ci     = (const float*)d_in[5];
    const float* D      = (const float*)d_in[6];
    const float* W      = (const float*)d_in[7];
    const float* bias   = (const float*)d_in[8];
    float* out = (float*)d_out;

    float* kernT;
    float* yy;
    cudaGetSymbolAddress((void**)&kernT, g_kernT);
    cudaGetSymbolAddress((void**)&yy, g_y);

    k_gen<<<HH, 32>>>(log_dt, Arl, Aim, Cr, Ci, kernT);

    dim3 cgrid(HH / CHT, LL / CLT, BB);
    k_conv<<<cgrid, 128>>>(x, kernT, D, yy);

    dim3 ggrid(1024 / 64, (BB * LL) / 128);
    k_gemm<<<ggrid, 256>>>(yy, W, bias, out);
}

// round 5
// speedup vs baseline: 1.4832x; 1.4656x over previous
#include <cuda_runtime.h>
#include <cuda_bf16.h>
#include <math.h>
#include <stdint.h>

#define BB 16
#define LL 1024
#define HH 1024
#define NN 64

// scratch (device globals — no allocation allowed)
__device__ float g_kernT[LL * HH];                     // kern transposed [l][h]
__device__ __nv_bfloat16 g_yh[BB * LL * HH];           // y hi (bf16)
__device__ __nv_bfloat16 g_yl[BB * LL * HH];           // y lo (bf16)
__device__ __nv_bfloat16 g_whT[2048 * 1024];           // W^T hi [n][k]
__device__ __nv_bfloat16 g_wlT[2048 * 1024];           // W^T lo [n][k]

// ---- packed fp32x2 helpers ------------------------------------------------
__device__ __forceinline__ unsigned long long ffma2(unsigned long long a,
                                                    unsigned long long b,
                                                    unsigned long long c) {
    unsigned long long d;
    asm("fma.rn.f32x2 %0, %1, %2, %3;" : "=l"(d) : "l"(a), "l"(b), "l"(c));
    return d;
}
__device__ __forceinline__ float2 unpack2(unsigned long long v) {
    float x, y;
    asm("mov.b64 {%0,%1}, %2;" : "=f"(x), "=f"(y) : "l"(v));
    return make_float2(x, y);
}

// ---- smem / cp.async / mma helpers (all non-'a' features) ------------------
__device__ __forceinline__ uint32_t smem_u32(const void* p) {
    uint32_t a;
    asm("{ .reg .u64 t; cvta.to.shared.u64 t, %1; cvt.u32.u64 %0, t; }"
        : "=r"(a) : "l"(p));
    return a;
}
#define CP_ASYNC16(dst, src) \
    asm volatile("cp.async.cg.shared.global [%0], [%1], 16;" :: "r"(dst), "l"(src))
#define CP_COMMIT() asm volatile("cp.async.commit_group;" ::: "memory")
#define CP_WAIT1() asm volatile("cp.async.wait_group 1;" ::: "memory")
#define CP_WAIT0() asm volatile("cp.async.wait_group 0;" ::: "memory")

__device__ __forceinline__ void ldsm_x4(uint32_t* r, uint32_t addr) {
    asm volatile("ldmatrix.sync.aligned.m8n8.x4.shared.b16 {%0,%1,%2,%3}, [%4];"
                 : "=r"(r[0]), "=r"(r[1]), "=r"(r[2]), "=r"(r[3]) : "r"(addr));
}
__device__ __forceinline__ void mma_bf16(float* c, const uint32_t* a,
                                         const uint32_t* b) {
    asm volatile(
        "mma.sync.aligned.m16n8k16.row.col.f32.bf16.bf16.f32 "
        "{%0,%1,%2,%3}, {%4,%5,%6,%7}, {%8,%9}, {%0,%1,%2,%3};"
        : "+f"(c[0]), "+f"(c[1]), "+f"(c[2]), "+f"(c[3])
        : "r"(a[0]), "r"(a[1]), "r"(a[2]), "r"(a[3]), "r"(b[0]), "r"(b[1]));
}

// ---------------------------------------------------------------------------
// Kernel 1: S4D kernel generation (unchanged).
// ---------------------------------------------------------------------------
__global__ void k_gen(const float* __restrict__ log_dt,
                      const float* __restrict__ Arl,
                      const float* __restrict__ Aim,
                      const float* __restrict__ Cr,
                      const float* __restrict__ Ci,
                      float* __restrict__ kernT) {
    int h = blockIdx.x;
    int lane = threadIdx.x;
    float dt = expf(log_dt[h]);

    float zr[2], zi[2], wr[2], wi[2];
#pragma unroll
    for (int t = 0; t < 2; t++) {
        int n = lane + t * 32;
        float ar = -expf(Arl[h * NN + n]);
        float ai = Aim[h * NN + n];
        float er = expf(dt * ar);
        float sn, cs;
        sincosf(dt * ai, &sn, &cs);
        float Er = er * cs - 1.0f, Ei = er * sn;
        float inv = 1.0f / (ar * ar + ai * ai);
        float Fr = (Er * ar + Ei * ai) * inv;
        float Fi = (Ei * ar - Er * ai) * inv;
        float cr = Cr[h * NN + n], ci = Ci[h * NN + n];
        zr[t] = cr * Fr - ci * Fi;
        zi[t] = cr * Fi + ci * Fr;
        wr[t] = er * cs;
        wi[t] = er * sn;
    }
    for (int l = 0; l < LL; l++) {
        float s = zr[0] + zr[1];
#pragma unroll
        for (int o = 16; o > 0; o >>= 1)
            s += __shfl_xor_sync(0xffffffffu, s, o);
        if (lane == 0) kernT[(size_t)l * HH + h] = 2.0f * s;
#pragma unroll
        for (int t = 0; t < 2; t++) {
            float tr = zr[t] * wr[t] - zi[t] * wi[t];
            zi[t] = zr[t] * wi[t] + zi[t] * wr[t];
            zr[t] = tr;
        }
    }
}

// ---------------------------------------------------------------------------
// Kernel 1b: W [1024,2048] f32 -> transposed bf16 hi/lo [2048][1024]
// ---------------------------------------------------------------------------
__global__ void k_prepW(const float* __restrict__ W,
                        __nv_bfloat16* __restrict__ whT,
                        __nv_bfloat16* __restrict__ wlT) {
    __shared__ float t[32][33];
    int tx = threadIdx.x, ty = threadIdx.y;
    int n0 = blockIdx.x * 32, k0 = blockIdx.y * 32;
#pragma unroll
    for (int i = 0; i < 4; i++)
        t[ty + i * 8][tx] = W[(size_t)(k0 + ty + i * 8) * 2048 + n0 + tx];
    __syncthreads();
#pragma unroll
    for (int i = 0; i < 4; i++) {
        int n = n0 + ty + i * 8;
        float v = t[tx][ty + i * 8];
        __nv_bfloat16 h = __float2bfloat16(v);
        float lo = v - __bfloat162float(h);
        whT[(size_t)n * 1024 + k0 + tx] = h;
        wlT[(size_t)n * 1024 + k0 + tx] = __float2bfloat16(lo);
    }
}

// ---------------------------------------------------------------------------
// Kernel 2: causal conv + D-skip + gelu; outputs bf16 hi/lo split of y.
// ---------------------------------------------------------------------------
#define CLT 128
#define CHT 32
#define CJC 64

__device__ __forceinline__ float gelu_tanh(float t) {
    float c = 0.7978845608028654f * (t + 0.044715f * t * t * t);
    return 0.5f * t * (1.0f + tanhf(c));
}

__global__ __launch_bounds__(128) void k_conv(const float* __restrict__ x,
                                              const float* __restrict__ kernT,
                                              const float* __restrict__ D,
                                              __nv_bfloat16* __restrict__ yh,
                                              __nv_bfloat16* __restrict__ yl) {
    __shared__ float ks[CJC][CHT];
    __shared__ float xs[192][CHT];

    int tid = threadIdx.x;
    int hb = (tid & 7) * 4;
    int lb = (tid >> 3) * 8;
    int H0 = blockIdx.x * CHT;
    int L0 = blockIdx.y * CLT;
    int b  = blockIdx.z;
    const float* xb = x + (size_t)b * LL * HH;

    unsigned long long acc2[8][2];
#pragma unroll
    for (int r = 0; r < 8; r++) { acc2[r][0] = 0ull; acc2[r][1] = 0ull; }

    for (int J0 = 0; J0 < L0 + CLT; J0 += CJC) {
        __syncthreads();
#pragma unroll
        for (int f = tid; f < 512; f += 128) {
            int j = f >> 3, h4 = (f & 7) * 4;
            *(float4*)&ks[j][h4] =
                *(const float4*)&kernT[(size_t)(J0 + j) * HH + H0 + h4];
        }
        int xbase = L0 - J0 - 63;
#pragma unroll
        for (int f = tid; f < 192 * 8; f += 128) {
            int row = f >> 3, h4 = (f & 7) * 4;
            int gl = xbase + row;
            float4 v = make_float4(0.f, 0.f, 0.f, 0.f);
            if (gl >= 0 && gl < LL)
                v = *(const float4*)&xb[(size_t)gl * HH + H0 + h4];
            *(float4*)&xs[row][h4] = v;
        }
        __syncthreads();

        ulonglong2 win[8];
#pragma unroll
        for (int i = 0; i < 8; i++)
            win[(63 + i) & 7] = *(ulonglong2*)&xs[lb + 63 + i][hb];

#pragma unroll 1
        for (int jj0 = 0; jj0 < 64; jj0 += 8) {
#pragma unroll
            for (int u = 0; u < 8; u++) {
                int jj = jj0 + u;
                ulonglong2 kp = *(ulonglong2*)&ks[jj][hb];
#pragma unroll
                for (int r = 0; r < 8; r++) {
                    ulonglong2 xv = win[(63 - u + r) & 7];
                    acc2[r][0] = ffma2(kp.x, xv.x, acc2[r][0]);
                    acc2[r][1] = ffma2(kp.y, xv.y, acc2[r][1]);
                }
                if (jj < 63)
                    win[(62 - u) & 7] = *(ulonglong2*)&xs[lb + 62 - jj][hb];
            }
        }
    }

    float4 dv = *(const float4*)&D[H0 + hb];
    float dd[4] = {dv.x, dv.y, dv.z, dv.w};
#pragma unroll
    for (int r = 0; r < 8; r++) {
        int l = L0 + lb + r;
        float4 xv = *(const float4*)&xb[(size_t)l * HH + H0 + hb];
        float xa[4] = {xv.x, xv.y, xv.z, xv.w};
        float2 p0 = unpack2(acc2[r][0]);
        float2 p1 = unpack2(acc2[r][1]);
        float av[4] = {p0.x, p0.y, p1.x, p1.y};
        __nv_bfloat16 hv[4], lv[4];
#pragma unroll
        for (int c = 0; c < 4; c++) {
            float t = gelu_tanh(av[c] + xa[c] * dd[c]);
            hv[c] = __float2bfloat16(t);
            lv[c] = __float2bfloat16(t - __bfloat162float(hv[c]));
        }
        size_t idx = (size_t)b * LL * HH + (size_t)l * HH + H0 + hb;
        *(__nv_bfloat162*)&yh[idx]     = __nv_bfloat162(hv[0], hv[1]);
        *(__nv_bfloat162*)&yh[idx + 2] = __nv_bfloat162(hv[2], hv[3]);
        *(__nv_bfloat162*)&yl[idx]     = __nv_bfloat162(lv[0], lv[1]);
        *(__nv_bfloat162*)&yl[idx + 2] = __nv_bfloat162(lv[2], lv[3]);
    }
}

// ---------------------------------------------------------------------------
// Kernel 3: mma.sync bf16x3 GEMM + bias + GLU.
// CTA tile 128m x 128 B-rows (= 64 output cols; even row = a, odd row = g so
// each accumulator thread holds its (a,g) pair in-register -> GLU is free).
// K staged 32 at a time, double-buffered cp.async. 8 warps, 64m x 32row each.
// B fragments via NON-trans ldmatrix: W^T is [n][k] (k contiguous), which is
// exactly the col-major B layout mma.row.col expects.
// ---------------------------------------------------------------------------
#define GPITCH 80                      // bytes per smem row (32 bf16 + pad)
#define GMATB (128 * GPITCH)           // 10240 B per matrix-buffer
#define GOFF_B (4 * GMATB)             // B region after A[2buf][2mat]
#define SMEM_GEMM (8 * GMATB)          // 81920 B total
#define GNS 32                         // K stages (1024/32)

__global__ __launch_bounds__(256, 1) void k_gemm_mma(
    const __nv_bfloat16* __restrict__ Yh, const __nv_bfloat16* __restrict__ Yl,
    const __nv_bfloat16* __restrict__ WhT, const __nv_bfloat16* __restrict__ WlT,
    const float* __restrict__ bias, float* __restrict__ out) {
    extern __shared__ __align__(128) char smem[];
    uint32_t sb = smem_u32(smem);
    int tid = threadIdx.x;
    int wid = tid >> 5;
    int lane = tid & 31;
    int wm = wid >> 2;                 // 0/1 -> m half
    int wn = wid & 3;                  // 0..3 -> 32 B-rows each
    int N0a = blockIdx.x * 64;         // 64 output cols per CTA
    int M0 = blockIdx.y * 128;

    float acc[4][4][4];
#pragma unroll
    for (int i = 0; i < 4; i++)
#pragma unroll
        for (int j = 0; j < 4; j++)
#pragma unroll
            for (int e = 0; e < 4; e++) acc[i][j][e] = 0.0f;

#define G_ISSUE(S)                                                              \
    {                                                                           \
        int _s = (S);                                                           \
        int _buf = _s & 1;                                                      \
        int K0 = _s * 32;                                                       \
        _Pragma("unroll") for (int it = 0; it < 8; it++) {                      \
            int i = tid + it * 256;                                             \
            int side = i >> 10;                                                 \
            int j = i & 1023;                                                   \
            int mat = j >> 9;                                                   \
            int r = (j >> 2) & 127;                                             \
            int g = j & 3;                                                      \
            const __nv_bfloat16* src;                                           \
            if (side == 0) {                                                    \
                src = (mat ? Yl : Yh) + (size_t)(M0 + r) * 1024 + K0 + g * 8;   \
            } else {                                                            \
                int n = (r & 1) ? (1024 + N0a + (r >> 1)) : (N0a + (r >> 1));   \
                src = (mat ? WlT : WhT) + (size_t)n * 1024 + K0 + g * 8;        \
            }                                                                   \
            uint32_t dst = sb + side * GOFF_B + (_buf * 2 + mat) * GMATB +      \
                           r * GPITCH + g * 16;                                 \
            CP_ASYNC16(dst, src);                                               \
        }                                                                       \
        CP_COMMIT();                                                            \
    }

    G_ISSUE(0);
#pragma unroll 1
    for (int s = 0; s < GNS; s++) {
        int buf = s & 1;
        if (s + 1 < GNS) {
            G_ISSUE(s + 1);
            CP_WAIT1();
        } else {
            CP_WAIT0();
        }
        __syncthreads();

        uint32_t aH = sb + (buf * 2 + 0) * GMATB;
        uint32_t aL = sb + (buf * 2 + 1) * GMATB;
        uint32_t bH = sb + GOFF_B + (buf * 2 + 0) * GMATB;
        uint32_t bL = sb + GOFF_B + (buf * 2 + 1) * GMATB;

#pragma unroll
        for (int kc = 0; kc < 2; kc++) {
            // A fragments: mats = (m0-7,k0-7),(m8-15,k0-7),(m0-7,k8-15),(m8-15,k8-15)
            uint32_t a_h[4][4], a_l[4][4];
            uint32_t arow = (wm * 64 + (lane & 15)) * GPITCH + kc * 32 +
                            (lane >> 4) * 16;
#pragma unroll
            for (int mf = 0; mf < 4; mf++) {
                ldsm_x4(a_h[mf], aH + arow + mf * 16 * GPITCH);
                ldsm_x4(a_l[mf], aL + arow + mf * 16 * GPITCH);
            }
            // B fragments, NON-trans: mats = (n0-7,k0-7),(n0-7,k8-15),
            // (n8-15,k0-7),(n8-15,k8-15) -> r0,r1 = b0,b1 of nf ; r2,r3 of nf+1
            uint32_t bh[4][2], bl[4][2];
            uint32_t boff = (((lane >> 4) & 1) * 8 + (lane & 7)) * GPITCH +
                            kc * 32 + ((lane >> 3) & 1) * 16;
#pragma unroll
            for (int q = 0; q < 2; q++) {
                uint32_t badr = (wn * 32 + q * 16) * GPITCH + boff;
                uint32_t t4[4];
                ldsm_x4(t4, bH + badr);
                bh[2 * q][0] = t4[0]; bh[2 * q][1] = t4[1];
                bh[2 * q + 1][0] = t4[2]; bh[2 * q + 1][1] = t4[3];
                ldsm_x4(t4, bL + badr);
                bl[2 * q][0] = t4[0]; bl[2 * q][1] = t4[1];
                bl[2 * q + 1][0] = t4[2]; bl[2 * q + 1][1] = t4[3];
            }
#pragma unroll
            for (int mf = 0; mf < 4; mf++)
#pragma unroll
                for (int nf = 0; nf < 4; nf++) {
                    mma_bf16(acc[mf][nf], a_h[mf], bh[nf]);
                    mma_bf16(acc[mf][nf], a_h[mf], bl[nf]);
                    mma_bf16(acc[mf][nf], a_l[mf], bh[nf]);
                }
        }
        __syncthreads();
    }

    // epilogue: bias + GLU, all register-local (even B-row = a, odd = g)
#pragma unroll
    for (int nf = 0; nf < 4; nf++) {
        int p = wn * 16 + nf * 4 + (lane & 3);
        int col = N0a + p;
        float ba = bias[col];
        float bg = bias[1024 + col];
#pragma unroll
        for (int mf = 0; mf < 4; mf++) {
            int m = M0 + wm * 64 + mf * 16 + (lane >> 2);
            float a0 = acc[mf][nf][0] + ba;
            float g0 = acc[mf][nf][1] + bg;
            float a1 = acc[mf][nf][2] + ba;
            float g1 = acc[mf][nf][3] + bg;
            out[(size_t)m * 1024 + col]       = a0 / (1.0f + expf(-g0));
            out[(size_t)(m + 8) * 1024 + col] = a1 / (1.0f + expf(-g1));
        }
    }
}

// ---------------------------------------------------------------------------
extern "C" void kernel_launch(void* const* d_in, const int* in_sizes, int n_in,
                              void* d_out, int out_size) {
    const float* x      = (const float*)d_in[0];
    const float* log_dt = (const float*)d_in[1];
    const float* Arl    = (const float*)d_in[2];
    const float* Aim    = (const float*)d_in[3];
    const float* Cr     = (const float*)d_in[4];
    const float* Ci     = (const float*)d_in[5];
    const float* D      = (const float*)d_in[6];
    const float* W      = (const float*)d_in[7];
    const float* bias   = (const float*)d_in[8];
    float* out = (float*)d_out;

    float* kernT;       __nv_bfloat16 *yh, *yl, *whT, *wlT;
    cudaGetSymbolAddress((void**)&kernT, g_kernT);
    cudaGetSymbolAddress((void**)&yh, g_yh);
    cudaGetSymbolAddress((void**)&yl, g_yl);
    cudaGetSymbolAddress((void**)&whT, g_whT);
    cudaGetSymbolAddress((void**)&wlT, g_wlT);

    cudaFuncSetAttribute(k_gemm_mma, cudaFuncAttributeMaxDynamicSharedMemorySize,
                         SMEM_GEMM);

    k_gen<<<HH, 32>>>(log_dt, Arl, Aim, Cr, Ci, kernT);
    k_prepW<<<dim3(2048 / 32, 1024 / 32), dim3(32, 8)>>>(W, whT, wlT);

    dim3 cgrid(HH / CHT, LL / CLT, BB);
    k_conv<<<cgrid, 128>>>(x, kernT, D, yh, yl);

    dim3 ggrid(16, 128);
    k_gemm_mma<<<ggrid, 256, SMEM_GEMM>>>(yh, yl, whT, wlT, bias, out);
}

// round 6
// speedup vs baseline: 1.9035x; 1.2834x over previous
#include <cuda_runtime.h>
#include <cuda_bf16.h>
#include <math.h>
#include <stdint.h>

#define BB 16
#define LL 1024
#define HH 1024
#define NN 64

typedef __nv_bfloat16 bf16;

// scratch (device globals — no allocation allowed)
__device__ float g_kern[HH * LL];              // kern [h][l]
__device__ bf16 g_xth[HH * BB * LL];           // x^T hi [h][b][l]
__device__ bf16 g_xtl[HH * BB * LL];           // x^T lo
__device__ bf16 g_yth[HH * BB * LL];           // y^T hi [h][b*l] (k-major for GEMM)
__device__ bf16 g_ytl[HH * BB * LL];           // y^T lo
__device__ bf16 g_whT[2048 * 1024];            // W^T hi [n][k]
__device__ bf16 g_wlT[2048 * 1024];            // W^T lo [n][k]

// ---- helpers ----------------------------------------------------------------
__device__ __forceinline__ uint32_t smem_u32(const void* p) {
    uint32_t a;
    asm("{ .reg .u64 t; cvta.to.shared.u64 t, %1; cvt.u32.u64 %0, t; }"
        : "=r"(a) : "l"(p));
    return a;
}
#define CP_ASYNC16(dst, src) \
    asm volatile("cp.async.cg.shared.global [%0], [%1], 16;" :: "r"(dst), "l"(src))
#define CP_COMMIT() asm volatile("cp.async.commit_group;" ::: "memory")
#define CP_WAIT1() asm volatile("cp.async.wait_group 1;" ::: "memory")
#define CP_WAIT0() asm volatile("cp.async.wait_group 0;" ::: "memory")

__device__ __forceinline__ void ldsm_x4(uint32_t* r, uint32_t addr) {
    asm volatile("ldmatrix.sync.aligned.m8n8.x4.shared.b16 {%0,%1,%2,%3}, [%4];"
                 : "=r"(r[0]), "=r"(r[1]), "=r"(r[2]), "=r"(r[3]) : "r"(addr));
}
__device__ __forceinline__ void ldsm_x4t(uint32_t* r, uint32_t addr) {
    asm volatile("ldmatrix.sync.aligned.m8n8.x4.trans.shared.b16 {%0,%1,%2,%3}, [%4];"
                 : "=r"(r[0]), "=r"(r[1]), "=r"(r[2]), "=r"(r[3]) : "r"(addr));
}
__device__ __forceinline__ void mma_bf16(float* c, const uint32_t* a,
                                         const uint32_t* b) {
    asm volatile(
        "mma.sync.aligned.m16n8k16.row.col.f32.bf16.bf16.f32 "
        "{%0,%1,%2,%3}, {%4,%5,%6,%7}, {%8,%9}, {%0,%1,%2,%3};"
        : "+f"(c[0]), "+f"(c[1]), "+f"(c[2]), "+f"(c[3])
        : "r"(a[0]), "r"(a[1]), "r"(a[2]), "r"(a[3]), "r"(b[0]), "r"(b[1]));
}
__device__ __forceinline__ float gelu_tanh(float t) {
    float c = 0.7978845608028654f * (t + 0.044715f * t * t * t);
    return 0.5f * t * (1.0f + tanhf(c));
}

// ---------------------------------------------------------------------------
// Kernel 1: S4D kernel generation -> kern[h][l]
// ---------------------------------------------------------------------------
__global__ void k_gen(const float* __restrict__ log_dt,
                      const float* __restrict__ Arl,
                      const float* __restrict__ Aim,
                      const float* __restrict__ Cr,
                      const float* __restrict__ Ci,
                      float* __restrict__ kern) {
    int h = blockIdx.x;
    int lane = threadIdx.x;
    float dt = expf(log_dt[h]);

    float zr[2], zi[2], wr[2], wi[2];
#pragma unroll
    for (int t = 0; t < 2; t++) {
        int n = lane + t * 32;
        float ar = -expf(Arl[h * NN + n]);
        float ai = Aim[h * NN + n];
        float er = expf(dt * ar);
        float sn, cs;
        sincosf(dt * ai, &sn, &cs);
        float Er = er * cs - 1.0f, Ei = er * sn;
        float inv = 1.0f / (ar * ar + ai * ai);
        float Fr = (Er * ar + Ei * ai) * inv;
        float Fi = (Ei * ar - Er * ai) * inv;
        float cr = Cr[h * NN + n], ci = Ci[h * NN + n];
        zr[t] = cr * Fr - ci * Fi;
        zi[t] = cr * Fi + ci * Fr;
        wr[t] = er * cs;
        wi[t] = er * sn;
    }
    for (int l = 0; l < LL; l++) {
        float s = zr[0] + zr[1];
#pragma unroll
        for (int o = 16; o > 0; o >>= 1)
            s += __shfl_xor_sync(0xffffffffu, s, o);
        if (lane == 0) kern[(size_t)h * LL + l] = 2.0f * s;
#pragma unroll
        for (int t = 0; t < 2; t++) {
            float tr = zr[t] * wr[t] - zi[t] * wi[t];
            zi[t] = zr[t] * wi[t] + zi[t] * wr[t];
            zr[t] = tr;
        }
    }
}

// ---------------------------------------------------------------------------
// Kernel 1b: W [1024,2048] -> W^T bf16 hi/lo [2048][1024]
// ---------------------------------------------------------------------------
__global__ void k_prepW(const float* __restrict__ W,
                        bf16* __restrict__ whT, bf16* __restrict__ wlT) {
    __shared__ float t[32][33];
    int tx = threadIdx.x, ty = threadIdx.y;
    int n0 = blockIdx.x * 32, k0 = blockIdx.y * 32;
#pragma unroll
    for (int i = 0; i < 4; i++)
        t[ty + i * 8][tx] = W[(size_t)(k0 + ty + i * 8) * 2048 + n0 + tx];
    __syncthreads();
#pragma unroll
    for (int i = 0; i < 4; i++) {
        int n = n0 + ty + i * 8;
        float v = t[tx][ty + i * 8];
        bf16 h = __float2bfloat16(v);
        float lo = v - __bfloat162float(h);
        whT[(size_t)n * 1024 + k0 + tx] = h;
        wlT[(size_t)n * 1024 + k0 + tx] = __float2bfloat16(lo);
    }
}

// ---------------------------------------------------------------------------
// Kernel 1c: x [b][l][h] f32 -> x^T bf16 hi/lo [h][b][l]
// ---------------------------------------------------------------------------
__global__ void k_xt(const float* __restrict__ x,
                     bf16* __restrict__ xth, bf16* __restrict__ xtl) {
    __shared__ float t[32][33];
    int tx = threadIdx.x, ty = threadIdx.y;
    int l0 = blockIdx.x * 32, h0 = blockIdx.y * 32, b = blockIdx.z;
    const float* xb = x + (size_t)b * LL * HH;
#pragma unroll
    for (int i = 0; i < 4; i++)
        t[ty + i * 8][tx] = xb[(size_t)(l0 + ty + i * 8) * HH + h0 + tx];
    __syncthreads();
#pragma unroll
    for (int i = 0; i < 4; i++) {
        int hh = ty + i * 8;
        float v = t[tx][hh];
        bf16 hi = __float2bfloat16(v);
        float lo = v - __bfloat162float(hi);
        size_t o = (size_t)(h0 + hh) * (BB * LL) + (size_t)b * LL + l0 + tx;
        xth[o] = hi;
        xtl[o] = __float2bfloat16(lo);
    }
}

// ---------------------------------------------------------------------------
// Kernel 2: Toeplitz tensor-core causal conv + D-skip + gelu.
// One CTA per h. y^T[h][b][lout] = gelu( sum_d T_d @ x_tile + x*D )
// T_d[r][c] = kern[h][64d + r - c] (0 if negative). bf16x3 split.
// Warp w owns lout tiles {w, 15-w}. Output written hi/lo to y^T.
// ---------------------------------------------------------------------------
#define XP 2064                       // x smem pitch (1024 bf16 + 8 pad)
#define TP 144                        // T smem pitch (64 bf16 + 8 pad)
#define SM_XH 0
#define SM_XL 33024
#define SM_K  66048                   // kern f32, 4 KB
#define SM_T  70144                   // [2 buf][2 mats][64*144=9216]
#define TBUF  18432
#define SMEM_CONV 107008

__global__ __launch_bounds__(256, 1) void k_conv_tc(
    const bf16* __restrict__ xth, const bf16* __restrict__ xtl,
    const float* __restrict__ kern, const float* __restrict__ D,
    bf16* __restrict__ yth, bf16* __restrict__ ytl) {
    extern __shared__ __align__(128) char smem[];
    uint32_t sb = smem_u32(smem);
    int tid = threadIdx.x;
    int wid = tid >> 5;
    int lane = tid & 31;
    int h = blockIdx.x;

    // async-load x hi/lo (16 b-rows x 2048 B each)
#pragma unroll
    for (int m = 0; m < 2; m++) {
        const bf16* s0 = (m ? xtl : xth) + (size_t)h * (BB * LL);
        uint32_t d0 = sb + (m ? SM_XL : SM_XH);
        for (int i = tid; i < 2048; i += 256) {
            int b = i >> 7, g = i & 127;
            CP_ASYNC16(d0 + b * XP + g * 16, s0 + (size_t)b * LL + g * 8);
        }
    }
    CP_COMMIT();

    float* ks = (float*)(smem + SM_K);
    for (int i = tid; i < 1024; i += 256) ks[i] = kern[(size_t)h * LL + i];
    __syncthreads();

    // build T_0 (buf 0) while x loads fly
    for (int i = tid; i < 4096; i += 256) {
        int r = i >> 6, c = i & 63;
        int off = r - c;
        float v = (off >= 0) ? ks[off] : 0.0f;
        bf16 hi = __float2bfloat16(v);
        bf16 lo = __float2bfloat16(v - __bfloat162float(hi));
        *(bf16*)(smem + SM_T + r * TP + c * 2) = hi;
        *(bf16*)(smem + SM_T + 9216 + r * TP + c * 2) = lo;
    }
    CP_WAIT0();
    __syncthreads();

    float acc[2][4][2][4];
#pragma unroll
    for (int t = 0; t < 2; t++)
#pragma unroll
        for (int mf = 0; mf < 4; mf++)
#pragma unroll
            for (int nf = 0; nf < 2; nf++)
#pragma unroll
                for (int e = 0; e < 4; e++) acc[t][mf][nf][e] = 0.0f;

#pragma unroll 1
    for (int d = 0; d < 16; d++) {
        int bufT = d & 1;
        if (d > 0) {
            __syncthreads();
            for (int i = tid; i < 4096; i += 256) {
                int r = i >> 6, c = i & 63;
                float v = ks[d * 64 + r - c];   // d>=1: offset always in [1,1023]
                bf16 hi = __float2bfloat16(v);
                bf16 lo = __float2bfloat16(v - __bfloat162float(hi));
                *(bf16*)(smem + SM_T + bufT * TBUF + r * TP + c * 2) = hi;
                *(bf16*)(smem + SM_T + bufT * TBUF + 9216 + r * TP + c * 2) = lo;
            }
            __syncthreads();
        }
        uint32_t tH = sb + SM_T + bufT * TBUF;
        uint32_t tL = tH + 9216;
#pragma unroll
        for (int t = 0; t < 2; t++) {
            int li = t ? (15 - wid) : wid;
            if (li < d) continue;
            int ji = li - d;
#pragma unroll
            for (int kc = 0; kc < 4; kc++) {
                uint32_t a_h[4][4], a_l[4][4];
                uint32_t arow = (lane & 15) * TP + kc * 32 + (lane >> 4) * 16;
#pragma unroll
                for (int mf = 0; mf < 4; mf++) {
                    ldsm_x4(a_h[mf], tH + mf * 16 * TP + arow);
                    ldsm_x4(a_l[mf], tL + mf * 16 * TP + arow);
                }
                uint32_t bh[2][2], bl[2][2];
                uint32_t boff = (((lane >> 4) & 1) * 8 + (lane & 7)) * XP +
                                ji * 128 + kc * 32 + ((lane >> 3) & 1) * 16;
                {
                    uint32_t t4[4];
                    ldsm_x4(t4, sb + SM_XH + boff);
                    bh[0][0] = t4[0]; bh[0][1] = t4[1];
                    bh[1][0] = t4[2]; bh[1][1] = t4[3];
                    ldsm_x4(t4, sb + SM_XL + boff);
                    bl[0][0] = t4[0]; bl[0][1] = t4[1];
                    bl[1][0] = t4[2]; bl[1][1] = t4[3];
                }
#pragma unroll
                for (int mf = 0; mf < 4; mf++)
#pragma unroll
                    for (int nf = 0; nf < 2; nf++) {
                        mma_bf16(acc[t][mf][nf], a_h[mf], bh[nf]);
                        mma_bf16(acc[t][mf][nf], a_h[mf], bl[nf]);
                        mma_bf16(acc[t][mf][nf], a_l[mf], bh[nf]);
                    }
            }
        }
    }

    // epilogue: per-warp smem bounce [16 b][64 l] (reuses T area), then
    // gelu(conv + x*D), bf16 hi/lo split, coalesced store to y^T.
    __syncthreads();
    float Dh = D[h];
    float* epf = (float*)(smem + SM_T + wid * 4352);  // pitch 272 B = 68 f32
#pragma unroll 1
    for (int t = 0; t < 2; t++) {
        int li = t ? (15 - wid) : wid;
        int r0 = lane >> 2, cc = (lane & 3) * 2;
#pragma unroll
        for (int mf = 0; mf < 4; mf++)
#pragma unroll
            for (int nf = 0; nf < 2; nf++) {
                int bq = nf * 8 + cc;
                int lq = mf * 16 + r0;
                epf[bq * 68 + lq]           = acc[t][mf][nf][0];
                epf[(bq + 1) * 68 + lq]     = acc[t][mf][nf][1];
                epf[bq * 68 + lq + 8]       = acc[t][mf][nf][2];
                epf[(bq + 1) * 68 + lq + 8] = acc[t][mf][nf][3];
            }
        __syncwarp();
#pragma unroll
        for (int i = lane; i < 1024; i += 32) {
            int b = i >> 6, l = i & 63;
            int lout = li * 64 + l;
            float xv = __bfloat162float(*(bf16*)(smem + SM_XH + b * XP + lout * 2)) +
                       __bfloat162float(*(bf16*)(smem + SM_XL + b * XP + lout * 2));
            float v = gelu_tanh(epf[b * 68 + l] + xv * Dh);
            bf16 hi = __float2bfloat16(v);
            bf16 lo = __float2bfloat16(v - __bfloat162float(hi));
            size_t o = (size_t)h * (BB * LL) + (size_t)b * LL + lout;
            yth[o] = hi;
            ytl[o] = lo;
        }
        __syncwarp();
    }
}

// ---------------------------------------------------------------------------
// Kernel 3: mma.sync bf16x3 GEMM + bias + GLU.
// A = y^T [k=h][m=b*l] via trans-ldmatrix; B = W^T [n][k] (a/g interleaved).
// CTA: 128m x 256 B-rows (=128 out cols); 8 warps each 64m x 64 B-rows.
// ---------------------------------------------------------------------------
#define GAP 272                         // A smem pitch (128 m bf16 + 8 pad)
#define GABUF (32 * GAP)                // 8704
#define GBP 80                          // B smem pitch (32 k bf16 + 8 pad)
#define GBBUF (256 * GBP)               // 20480
#define SM_GA 0                         // [2 buf][2 mat][GABUF] = 34816
#define SM_GB 34816                     // [2 buf][2 mat][GBBUF] = 81920
#define SMEM_GEMM 116736
#define GNS 32                          // K stages (1024/32)

__global__ __launch_bounds__(256, 1) void k_gemm_mma(
    const bf16* __restrict__ Yth, const bf16* __restrict__ Ytl,
    const bf16* __restrict__ WhT, const bf16* __restrict__ WlT,
    const float* __restrict__ bias, float* __restrict__ out) {
    extern __shared__ __align__(128) char smem[];
    uint32_t sb = smem_u32(smem);
    int tid = threadIdx.x;
    int wid = tid >> 5;
    int lane = tid & 31;
    int wm = wid >> 2;                  // 0/1
    int wn = wid & 3;                   // 0..3
    int N0a = blockIdx.x * 128;         // 128 output cols per CTA
    int M0 = blockIdx.y * 128;

    float acc[4][8][4];
#pragma unroll
    for (int i = 0; i < 4; i++)
#pragma unroll
        for (int j = 0; j < 8; j++)
#pragma unroll
            for (int e = 0; e < 4; e++) acc[i][j][e] = 0.0f;

#define G_ISSUE(S)                                                              \
    {                                                                           \
        int _s = (S);                                                           \
        int _buf = _s & 1;                                                      \
        int K0 = _s * 32;                                                       \
        _Pragma("unroll") for (int it = 0; it < 12; it++) {                     \
            int i = tid + it * 256;                                             \
            const bf16* src;                                                    \
            uint32_t dst;                                                       \
            if (i < 1024) {                                                     \
                int mat = i >> 9, r = (i >> 4) & 31, g = i & 15;                \
                src = (mat ? Ytl : Yth) + (size_t)(K0 + r) * 16384 + M0 + g * 8;\
                dst = sb + SM_GA + (_buf * 2 + mat) * GABUF + r * GAP + g * 16; \
            } else {                                                            \
                int j = i - 1024;                                               \
                int mat = j >> 10, r = (j >> 2) & 255, g = j & 3;               \
                int n = (r & 1) ? (1024 + N0a + (r >> 1)) : (N0a + (r >> 1));   \
                src = (mat ? WlT : WhT) + (size_t)n * 1024 + K0 + g * 8;        \
                dst = sb + SM_GB + (_buf * 2 + mat) * GBBUF + r * GBP + g * 16; \
            }                                                                   \
            CP_ASYNC16(dst, src);                                               \
        }                                                                       \
        CP_COMMIT();                                                            \
    }

    G_ISSUE(0);
#pragma unroll 1
    for (int s = 0; s < GNS; s++) {
        int buf = s & 1;
        if (s + 1 < GNS) {
            G_ISSUE(s + 1);
            CP_WAIT1();
        } else {
            CP_WAIT0();
        }
        __syncthreads();

        uint32_t aHb = sb + SM_GA + (buf * 2 + 0) * GABUF;
        uint32_t aLb = sb + SM_GA + (buf * 2 + 1) * GABUF;
        uint32_t bHb = sb + SM_GB + (buf * 2 + 0) * GBBUF;
        uint32_t bLb = sb + SM_GB + (buf * 2 + 1) * GBBUF;

#pragma unroll
        for (int kc = 0; kc < 2; kc++) {
            // A fragments via trans-ldmatrix from [k][m] smem:
            // lanes 0-7: k0-7/m0-7, 8-15: k0-7/m8-15, 16-23: k8-15/m0-7,
            // 24-31: k8-15/m8-15  -> a0..a3 in mma order.
            uint32_t a_h[4][4], a_l[4][4];
            uint32_t arow = (kc * 16 + ((lane >> 4) & 1) * 8 + (lane & 7)) * GAP;
#pragma unroll
            for (int mf = 0; mf < 4; mf++) {
                uint32_t ao = arow + (wm * 64 + mf * 16 + ((lane >> 3) & 1) * 8) * 2;
                ldsm_x4t(a_h[mf], aHb + ao);
                ldsm_x4t(a_l[mf], aLb + ao);
            }
            uint32_t boff = (((lane >> 4) & 1) * 8 + (lane & 7)) * GBP +
                            kc * 32 + ((lane >> 3) & 1) * 16;
#pragma unroll
            for (int q = 0; q < 4; q++) {
                uint32_t badr = (wn * 64 + q * 16) * GBP + boff;
                uint32_t bh[2][2], bl[2][2];
                uint32_t t4[4];
                ldsm_x4(t4, bHb + badr);
                bh[0][0] = t4[0]; bh[0][1] = t4[1];
                bh[1][0] = t4[2]; bh[1][1] = t4[3];
                ldsm_x4(t4, bLb + badr);
                bl[0][0] = t4[0]; bl[0][1] = t4[1];
                bl[1][0] = t4[2]; bl[1][1] = t4[3];
#pragma unroll
                for (int mf = 0; mf < 4; mf++)
#pragma unroll
                    for (int e = 0; e < 2; e++) {
                        int nf = 2 * q + e;
                        mma_bf16(acc[mf][nf], a_h[mf], bh[e]);
                        mma_bf16(acc[mf][nf], a_h[mf], bl[e]);
                        mma_bf16(acc[mf][nf], a_l[mf], bh[e]);
                    }
            }
        }
        __syncthreads();
    }

    // epilogue: bias + GLU (even B-row = a, odd = g, register-local pair)
#pragma unroll
    for (int nf = 0; nf < 8; nf++) {
        int p = wn * 32 + nf * 4 + (lane & 3);
        int col = N0a + p;
        float ba = bias[col];
        float bg = bias[1024 + col];
#pragma unroll
        for (int mf = 0; mf < 4; mf++) {
            int m = M0 + wm * 64 + mf * 16 + (lane >> 2);
            float a0 = acc[mf][nf][0] + ba;
            float g0 = acc[mf][nf][1] + bg;
            float a1 = acc[mf][nf][2] + ba;
            float g1 = acc[mf][nf][3] + bg;
            out[(size_t)m * 1024 + col]       = a0 / (1.0f + expf(-g0));
            out[(size_t)(m + 8) * 1024 + col] = a1 / (1.0f + expf(-g1));
        }
    }
}

// ---------------------------------------------------------------------------
extern "C" void kernel_launch(void* const* d_in, const int* in_sizes, int n_in,
                              void* d_out, int out_size) {
    const float* x      = (const float*)d_in[0];
    const float* log_dt = (const float*)d_in[1];
    const float* Arl    = (const float*)d_in[2];
    const float* Aim    = (const float*)d_in[3];
    const float* Cr     = (const float*)d_in[4];
    const float* Ci     = (const float*)d_in[5];
    const float* D      = (const float*)d_in[6];
    const float* W      = (const float*)d_in[7];
    const float* bias   = (const float*)d_in[8];
    float* out = (float*)d_out;

    float* kern;
    bf16 *xth, *xtl, *yth, *ytl, *whT, *wlT;
    cudaGetSymbolAddress((void**)&kern, g_kern);
    cudaGetSymbolAddress((void**)&xth, g_xth);
    cudaGetSymbolAddress((void**)&xtl, g_xtl);
    cudaGetSymbolAddress((void**)&yth, g_yth);
    cudaGetSymbolAddress((void**)&ytl, g_ytl);
    cudaGetSymbolAddress((void**)&whT, g_whT);
    cudaGetSymbolAddress((void**)&wlT, g_wlT);

    cudaFuncSetAttribute(k_conv_tc, cudaFuncAttributeMaxDynamicSharedMemorySize,
                         SMEM_CONV);
    cudaFuncSetAttribute(k_gemm_mma, cudaFuncAttributeMaxDynamicSharedMemorySize,
                         SMEM_GEMM);

    k_gen<<<HH, 32>>>(log_dt, Arl, Aim, Cr, Ci, kern);
    k_prepW<<<dim3(2048 / 32, 1024 / 32), dim3(32, 8)>>>(W, whT, wlT);
    k_xt<<<dim3(LL / 32, HH / 32, BB), dim3(32, 8)>>>(x, xth, xtl);

    k_conv_tc<<<HH, 256, SMEM_CONV>>>(xth, xtl, kern, D, yth, ytl);

    dim3 ggrid(2048 / 256, 16384 / 128);   // (8, 128)
    k_gemm_mma<<<ggrid, 256, SMEM_GEMM>>>(yth, ytl, whT, wlT, bias, out);
}